// round 5
// baseline (speedup 1.0000x reference)
#include <cuda_runtime.h>

#define NEU   64
#define HID   32
#define GD    103
#define N_MAX 2000128
#define B_MAX 8192

typedef unsigned long long ull;

// Scratch (no allocations allowed in kernel_launch)
__device__ float        g_logit[N_MAX];
__device__ float        g_G[B_MAX * HID];
__device__ unsigned int g_maxenc[B_MAX];
__device__ float        g_sum[B_MAX];

// Monotonic float <-> uint encoding for atomicMax on floats
__device__ __forceinline__ unsigned int enc_f(float f) {
    unsigned int u = __float_as_uint(f);
    return (u & 0x80000000u) ? ~u : (u | 0x80000000u);
}
__device__ __forceinline__ float dec_f(unsigned int u) {
    u = (u & 0x80000000u) ? (u & 0x7FFFFFFFu) : ~u;
    return __uint_as_float(u);
}

// Packed f32x2 helpers (FFMA2 — only reachable via PTX)
__device__ __forceinline__ ull fma2(ull a, ull b, ull c) {
    ull d;
    asm("fma.rn.f32x2 %0, %1, %2, %3;" : "=l"(d) : "l"(a), "l"(b), "l"(c));
    return d;
}
__device__ __forceinline__ ull pack2(float lo, float hi) {
    ull d;
    asm("mov.b64 %0, {%1, %2};" : "=l"(d) : "f"(lo), "f"(hi));
    return d;
}
__device__ __forceinline__ void unpack2(ull v, float& lo, float& hi) {
    asm("mov.b64 {%0, %1}, %2;" : "=f"(lo), "=f"(hi) : "l"(v));
}

// ---------------------------------------------------------------------------
// k_init
// ---------------------------------------------------------------------------
__global__ void k_init(int b) {
    int i = blockIdx.x * blockDim.x + threadIdx.x;
    if (i < b) {
        g_maxenc[i] = 0u;      // encodes <= -inf
        g_sum[i]    = 0.0f;
    }
}

// ---------------------------------------------------------------------------
// k_graph: G[b][h] = b1[h] + sum_d global_fea[b][d] * W1[(64+d)][h]
// ---------------------------------------------------------------------------
__global__ void k_graph(const float* __restrict__ gf,
                        const float* __restrict__ W1,
                        const float* __restrict__ b1, int b) {
    int warp = (blockIdx.x * blockDim.x + threadIdx.x) >> 5;
    int lane = threadIdx.x & 31;
    if (warp >= b) return;

    const float* row = gf + (size_t)warp * GD;
    float r0 = row[lane];
    float r1 = row[32 + lane];
    float r2 = row[64 + lane];
    float r3 = (lane < (GD - 96)) ? row[96 + lane] : 0.0f;

    float acc = b1[lane];
#pragma unroll
    for (int d = 0; d < GD; d++) {
        float v;
        if      (d < 32) v = __shfl_sync(0xFFFFFFFFu, r0, d);
        else if (d < 64) v = __shfl_sync(0xFFFFFFFFu, r1, d - 32);
        else if (d < 96) v = __shfl_sync(0xFFFFFFFFu, r2, d - 64);
        else             v = __shfl_sync(0xFFFFFFFFu, r3, d - 96);
        acc = fmaf(v, W1[(NEU + d) * HID + lane], acc);
    }
    g_G[warp * HID + lane] = acc;
}

// ---------------------------------------------------------------------------
// k_logits v3: smem-staged coalesced x + NT=2 nodes/thread + f32x2 GEMV
//
// Per warp-tile: 64 nodes. Staging transposes x into tile[k2][node] (b64
// pairs (x_{2k},x_{2k+1})), stride 66 to break STS bank conflicts.
// Thread handles nodes (2*lane, 2*lane+1): one LDS.128 per k2 yields both
// nodes' k-pair; weight LDS.128 (2 h-pairs) is reused for both nodes.
// ---------------------------------------------------------------------------
#define TPB      128
#define WARPS    (TPB / 32)
#define TILE_N   64
#define TSTRIDE  66                       // b64 units per k2 row
#define TILE_U64 (32 * TSTRIDE)           // 2112 b64 = 16896 B per warp
#define SMEM_W1  (32 * 32)                // 1024 b64 = 8 KB
#define SMEM_BYTES (SMEM_W1 * 8 + 256 + WARPS * TILE_U64 * 8)

__global__ void __launch_bounds__(TPB, 2)
k_logits(const float* __restrict__ x,
         const int* __restrict__ nb,
         const float* __restrict__ W1,
         const float* __restrict__ W2,
         const float* __restrict__ b2, int n) {
    extern __shared__ char smem[];
    ull*   sW1p = (ull*)smem;                       // [k2][h] = (W1[2k2][h], W1[2k2+1][h])
    float* sW2  = (float*)(smem + SMEM_W1 * 8);     // 32 floats
    float* sb2p = (float*)(smem + SMEM_W1 * 8 + 128);
    ull*   tiles = (ull*)(smem + SMEM_W1 * 8 + 256);

    for (int t = threadIdx.x; t < SMEM_W1; t += TPB) {
        int k2 = t >> 5, h = t & 31;
        sW1p[t] = pack2(W1[(2 * k2) * HID + h], W1[(2 * k2 + 1) * HID + h]);
    }
    if (threadIdx.x < HID) sW2[threadIdx.x] = W2[threadIdx.x];
    if (threadIdx.x == 0)  sb2p[0] = b2[0];
    __syncthreads();
    float sb2 = sb2p[0];

    int warp = threadIdx.x >> 5;
    int lane = threadIdx.x & 31;
    ull* tile = tiles + warp * TILE_U64;

    int gwarp  = blockIdx.x * WARPS + warp;
    int nwarps = gridDim.x * WARPS;
    int ntiles = (n + TILE_N - 1) / TILE_N;

    int m    = lane & 15;       // k-chunk index within row (floats 4m..4m+3)
    int half = lane >> 4;       // which of the two rows per 512B round

    for (int t = gwarp; t < ntiles; t += nwarps) {
        long node0 = (long)t * TILE_N;

        // ---- stage: coalesced gmem -> transposed smem tile ----
#pragma unroll 4
        for (int c = 0; c < 32; c++) {
            int  nl = 2 * c + half;
            long gn = node0 + nl;
            if (gn > n - 1) gn = n - 1;                 // clamp (dup reads, safe)
            float4 v = *(const float4*)(x + gn * NEU + m * 4);
            tile[(2 * m)     * TSTRIDE + nl] = pack2(v.x, v.y);
            tile[(2 * m + 1) * TSTRIDE + nl] = pack2(v.z, v.w);
        }
        __syncwarp();

        // ---- compute: 2 nodes per thread ----
        long gA = node0 + 2 * lane;
        long gB = gA + 1;
        bool vA = gA < n, vB = gB < n;
        int  segA = vA ? nb[gA] : 0;
        int  segB = vB ? nb[gB] : 0;

        ull accA[HID], accB[HID];
        {
            const float4* GA = (const float4*)(g_G + segA * HID);
            const float4* GB = (const float4*)(g_G + segB * HID);
#pragma unroll
            for (int q = 0; q < 8; q++) {
                float4 a = GA[q], b = GB[q];
                accA[4*q+0] = pack2(a.x, 0.f); accA[4*q+1] = pack2(a.y, 0.f);
                accA[4*q+2] = pack2(a.z, 0.f); accA[4*q+3] = pack2(a.w, 0.f);
                accB[4*q+0] = pack2(b.x, 0.f); accB[4*q+1] = pack2(b.y, 0.f);
                accB[4*q+2] = pack2(b.z, 0.f); accB[4*q+3] = pack2(b.w, 0.f);
            }
        }

        const ulonglong2* xrow = (const ulonglong2*)(tile + 2 * lane);
        for (int k2 = 0; k2 < 32; k2++) {
            // (xA pair, xB pair) for this k2 — one LDS.128
            ulonglong2 xq = *(const ulonglong2*)(tile + k2 * TSTRIDE + 2 * lane);
            const ulonglong2* wrow = (const ulonglong2*)(sW1p + k2 * HID);
#pragma unroll
            for (int h2 = 0; h2 < 16; h2++) {
                ulonglong2 w = wrow[h2];                 // h = 2h2, 2h2+1
                accA[2*h2]   = fma2(xq.x, w.x, accA[2*h2]);
                accA[2*h2+1] = fma2(xq.x, w.y, accA[2*h2+1]);
                accB[2*h2]   = fma2(xq.y, w.x, accB[2*h2]);
                accB[2*h2+1] = fma2(xq.y, w.y, accB[2*h2+1]);
            }
        }
        (void)xrow;

        // ---- tail: softplus + dot(W2) ----
        float lgA = sb2, lgB = sb2;
#pragma unroll
        for (int h = 0; h < HID; h++) {
            float lo, hi, a, sp;
            unpack2(accA[h], lo, hi);
            a  = lo + hi;
            sp = (a > 20.0f) ? a : __logf(1.0f + __expf(a));
            lgA = fmaf(sp, sW2[h], lgA);
            unpack2(accB[h], lo, hi);
            a  = lo + hi;
            sp = (a > 20.0f) ? a : __logf(1.0f + __expf(a));
            lgB = fmaf(sp, sW2[h], lgB);
        }

        if (vA) g_logit[gA] = lgA;
        if (vB) g_logit[gB] = lgB;

        if (vA && vB && segA == segB) {
            atomicMax(&g_maxenc[segA], enc_f(fmaxf(lgA, lgB)));
        } else {
            if (vA) atomicMax(&g_maxenc[segA], enc_f(lgA));
            if (vB) atomicMax(&g_maxenc[segB], enc_f(lgB));
        }
        __syncwarp();
    }
}

// ---------------------------------------------------------------------------
// k_exp: e = exp(logit - max[seg]); segmented atomicAdd of sums
// ---------------------------------------------------------------------------
__global__ void __launch_bounds__(256)
k_exp(const int* __restrict__ nb, int n) {
    int i = blockIdx.x * blockDim.x + threadIdx.x;
    int lane = threadIdx.x & 31;

    int   seg = -1;
    float e   = 0.0f;
    if (i < n) {
        seg = nb[i];
        float mx = dec_f(g_maxenc[seg]);
        e = __expf(g_logit[i] - mx);
    }

#pragma unroll
    for (int off = 1; off < 32; off <<= 1) {
        int   oseg = __shfl_down_sync(0xFFFFFFFFu, seg, off);
        float oe   = __shfl_down_sync(0xFFFFFFFFu, e,   off);
        if (lane + off < 32 && oseg == seg) e += oe;
    }
    int  pseg = __shfl_up_sync(0xFFFFFFFFu, seg, 1);
    bool head = (lane == 0) || (pseg != seg);
    if (head && seg >= 0) atomicAdd(&g_sum[seg], e);
}

// ---------------------------------------------------------------------------
// k_div: out = exp(logit - max[seg]) / sum[seg]   (recompute, same bits)
// ---------------------------------------------------------------------------
__global__ void __launch_bounds__(256)
k_div(const int* __restrict__ nb, float* __restrict__ out, int n) {
    int i = blockIdx.x * blockDim.x + threadIdx.x;
    if (i < n) {
        int   seg = nb[i];
        float mx  = dec_f(g_maxenc[seg]);
        float e   = __expf(g_logit[i] - mx);
        out[i] = e / g_sum[seg];
    }
}

// ---------------------------------------------------------------------------
extern "C" void kernel_launch(void* const* d_in, const int* in_sizes, int n_in,
                              void* d_out, int out_size) {
    const float* x   = (const float*)d_in[0];
    const int*   nb  = (const int*)d_in[1];
    const float* gf  = (const float*)d_in[2];
    const float* W1  = (const float*)d_in[3];
    const float* b1  = (const float*)d_in[4];
    const float* W2  = (const float*)d_in[5];
    const float* b2  = (const float*)d_in[6];
    float*       out = (float*)d_out;

    int n = in_sizes[0] / NEU;   // nodes
    int b = in_sizes[2] / GD;    // graphs

    k_init<<<(b + 255) / 256, 256>>>(b);
    k_graph<<<(b + 7) / 8, 256>>>(gf, W1, b1, b);

    static int smem_set = 0;
    if (!smem_set) {
        cudaFuncSetAttribute(k_logits, cudaFuncAttributeMaxDynamicSharedMemorySize,
                             SMEM_BYTES);
        smem_set = 1;
    }
    k_logits<<<296, TPB, SMEM_BYTES>>>(x, nb, W1, W2, b2, n);

    int blocks = (n + 255) / 256;
    k_exp<<<blocks, 256>>>(nb, n);
    k_div<<<blocks, 256>>>(nb, out, n);
}